// round 1
// baseline (speedup 1.0000x reference)
#include <cuda_runtime.h>

// Problem dims
#define A_DIM 32
#define R_DIM 2
#define T_DIM 4
#define S_DIM 14
#define F_DIM 3072
#define RB_DIM 256
#define NSITES (A_DIM * S_DIM * RB_DIM)   // 114688

#define BETA 2.71765f                      // 4.4492*ER^2 + 4.5655*ER + 1.2982, ER=0.25
#define SNR_LIN 10.0f

// Scratch (no allocation allowed)
__device__ float2 g_avg[NSITES * 8];       // [site][r*4+t], site = (a*14+s)*256+rb
__device__ float  g_R[32];                 // 4x4 complex R_{tu} = sum h_t conj(h_u), interleaved re/im
__device__ float  g_nv[32];                // noise variance per precoder
__device__ float2 g_W[32 * 4];             // codebook

static __device__ __forceinline__ float2 cmul(float2 a, float2 b) {
    return make_float2(a.x * b.x - a.y * b.y, a.x * b.y + a.y * b.x);
}

// ---------------------------------------------------------------------------
// K1: average groups of 12 subcarriers -> site-major avg layout.
// grid: 32a * 14s * 8rbt = 3584 blocks, block (32 rbl, 8 rt)
// ---------------------------------------------------------------------------
__global__ void k1_rb_average(const float* __restrict__ hre,
                              const float* __restrict__ him) {
    int b = blockIdx.x;
    int rbt = b & 7;
    int s   = (b >> 3) % 14;
    int a   = b / 112;
    int rbl = threadIdx.x;      // 0..31
    int rt  = threadIdx.y;      // 0..7  (r*4+t)
    int r = rt >> 2, t = rt & 3;

    int base = ((((a * 2 + r) * 4 + t) * 14) + s) * F_DIM + (rbt * 32 + rbl) * 12;

    float4 r0 = *(const float4*)(hre + base);
    float4 r1 = *(const float4*)(hre + base + 4);
    float4 r2 = *(const float4*)(hre + base + 8);
    float4 i0 = *(const float4*)(him + base);
    float4 i1 = *(const float4*)(him + base + 4);
    float4 i2 = *(const float4*)(him + base + 8);

    float sr = (r0.x + r0.y) + (r0.z + r0.w) + (r1.x + r1.y) + (r1.z + r1.w)
             + (r2.x + r2.y) + (r2.z + r2.w);
    float si = (i0.x + i0.y) + (i0.z + i0.w) + (i1.x + i1.y) + (i1.z + i1.w)
             + (i2.x + i2.y) + (i2.z + i2.w);

    __shared__ float2 tile[32][9];
    tile[rbl][rt] = make_float2(sr * (1.0f / 12.0f), si * (1.0f / 12.0f));
    __syncthreads();

    int q   = rt * 32 + rbl;          // 0..255
    int lo  = q >> 3;                 // local site 0..31
    int rt2 = q & 7;
    int siteBase = (a * 14 + s) * 256 + rbt * 32;
    g_avg[(siteBase + lo) * 8 + rt2] = tile[lo][rt2];

    if (b == 0 && q < 32) g_R[q] = 0.0f;   // zero R before K2 (stream-ordered)
}

// ---------------------------------------------------------------------------
// K2: accumulate R_{tu} = sum over sites,r of h_t * conj(h_u)
// grid: 448 blocks of 256 (exactly NSITES threads)
// ---------------------------------------------------------------------------
__global__ void k2_accum_R() {
    int site = blockIdx.x * 256 + threadIdx.x;
    float2 h[8];
    const float4* p = (const float4*)(g_avg + site * 8);
    float4 v0 = p[0], v1 = p[1], v2 = p[2], v3 = p[3];
    h[0] = make_float2(v0.x, v0.y); h[1] = make_float2(v0.z, v0.w);
    h[2] = make_float2(v1.x, v1.y); h[3] = make_float2(v1.z, v1.w);
    h[4] = make_float2(v2.x, v2.y); h[5] = make_float2(v2.z, v2.w);
    h[6] = make_float2(v3.x, v3.y); h[7] = make_float2(v3.z, v3.w);

    float accRe[16], accIm[16];
#pragma unroll
    for (int t = 0; t < 4; t++) {
#pragma unroll
        for (int u = 0; u < 4; u++) {
            float re = 0.f, im = 0.f;
#pragma unroll
            for (int r = 0; r < 2; r++) {
                float2 x = h[r * 4 + t], y = h[r * 4 + u];
                re += x.x * y.x + x.y * y.y;   // x * conj(y)
                im += x.y * y.x - x.x * y.y;
            }
            accRe[t * 4 + u] = re;
            accIm[t * 4 + u] = im;
        }
    }

    __shared__ float red[8][32];
    int lane = threadIdx.x & 31, wid = threadIdx.x >> 5;
#pragma unroll
    for (int k = 0; k < 16; k++) {
        float vr = accRe[k], vi = accIm[k];
#pragma unroll
        for (int o = 16; o > 0; o >>= 1) {
            vr += __shfl_down_sync(0xffffffffu, vr, o);
            vi += __shfl_down_sync(0xffffffffu, vi, o);
        }
        if (lane == 0) { red[wid][2 * k] = vr; red[wid][2 * k + 1] = vi; }
    }
    __syncthreads();
    if (threadIdx.x < 32) {
        float v = 0.f;
#pragma unroll
        for (int w = 0; w < 8; w++) v += red[w][threadIdx.x];
        atomicAdd(&g_R[threadIdx.x], v);
    }
}

// ---------------------------------------------------------------------------
// K3: codebook + n_var per precoder.  1 block, 32 threads.
// ---------------------------------------------------------------------------
__global__ void k3_codebook_nv() {
    int c = threadIdx.x;
    int l = c >> 2, n = c & 3;
    float th = 0.78539816339744831f * (float)l;  // pi*l/4
    float cs, sn;
    __sincosf(th, &sn, &cs);
    float2 e   = make_float2(cs, sn);
    float2 phi = make_float2((n == 0) ? 1.f : (n == 2) ? -1.f : 0.f,
                             (n == 1) ? 1.f : (n == 3) ? -1.f : 0.f);
    float2 w[4];
    w[0] = make_float2(0.5f, 0.0f);
    w[1] = make_float2(0.5f * e.x, 0.5f * e.y);
    w[2] = make_float2(0.5f * phi.x, 0.5f * phi.y);
    float2 pe = cmul(phi, e);
    w[3] = make_float2(0.5f * pe.x, 0.5f * pe.y);
#pragma unroll
    for (int t = 0; t < 4; t++) g_W[c * 4 + t] = w[t];

    // g_mean contribution: real( sum_{t,u} w_t conj(w_u) R_{tu} )
    float acc = 0.f;
#pragma unroll
    for (int t = 0; t < 4; t++) {
#pragma unroll
        for (int u = 0; u < 4; u++) {
            float Rre = g_R[2 * (t * 4 + u)];
            float Rim = g_R[2 * (t * 4 + u) + 1];
            // z = w_t * conj(w_u)
            float zre = w[t].x * w[u].x + w[t].y * w[u].y;
            float zim = w[t].y * w[u].x - w[t].x * w[u].y;
            acc += zre * Rre - zim * Rim;
        }
    }
    g_nv[c] = acc / ((float)NSITES * SNR_LIN);
}

// ---------------------------------------------------------------------------
// K4: per-RB sinr/exp reduction over (a,s) for all 32 precoders, then
// rate, argmax, and output write.  grid 256 blocks, 448 threads.
// ---------------------------------------------------------------------------
__global__ void k4_main(float* __restrict__ out, int out_size) {
    int rb  = blockIdx.x;
    int tid = threadIdx.x;          // 448 = 32a * 14s
    int a = tid & 31;
    int s = tid >> 5;
    int site = (a * 14 + s) * 256 + rb;

    float2 h[8];
    const float4* p = (const float4*)(g_avg + site * 8);
    float4 v0 = p[0], v1 = p[1], v2 = p[2], v3 = p[3];
    h[0] = make_float2(v0.x, v0.y); h[1] = make_float2(v0.z, v0.w);
    h[2] = make_float2(v1.x, v1.y); h[3] = make_float2(v1.z, v1.w);
    h[4] = make_float2(v2.x, v2.y); h[5] = make_float2(v2.z, v2.w);
    h[6] = make_float2(v3.x, v3.y); h[7] = make_float2(v3.z, v3.w);

    __shared__ float es[32];
    if (tid < 32) es[tid] = 0.f;
    __syncthreads();

    const float invbeta = 1.0f / BETA;

    for (int c = 0; c < 32; c++) {
        const float4* wp = (const float4*)(g_W + c * 4);
        float4 wa = wp[0], wb = wp[1];
        float2 w0 = make_float2(wa.x, wa.y), w1 = make_float2(wa.z, wa.w);
        float2 w2 = make_float2(wb.x, wb.y), w3 = make_float2(wb.z, wb.w);

        float2 e0 = cmul(h[0], w0);
        float2 t1 = cmul(h[1], w1); e0.x += t1.x; e0.y += t1.y;
        float2 t2 = cmul(h[2], w2); e0.x += t2.x; e0.y += t2.y;
        float2 t3 = cmul(h[3], w3); e0.x += t3.x; e0.y += t3.y;

        float2 e1 = cmul(h[4], w0);
        float2 u1 = cmul(h[5], w1); e1.x += u1.x; e1.y += u1.y;
        float2 u2 = cmul(h[6], w2); e1.x += u2.x; e1.y += u2.y;
        float2 u3 = cmul(h[7], w3); e1.x += u3.x; e1.y += u3.y;

        float g = e0.x * e0.x + e0.y * e0.y + e1.x * e1.x + e1.y * e1.y;
        float sx = e0.x + e1.x, sy = e0.y + e1.y;
        float u = sx * sx + sy * sy;
        float nv = g_nv[c];

        float Q  = g * g + nv * u;
        float rp = g * g * g + 2.0f * nv * u * (g + nv);
        float sinr = (Q * Q) / (nv * rp);
        float pv = __expf(-sinr * invbeta);

#pragma unroll
        for (int o = 16; o > 0; o >>= 1)
            pv += __shfl_down_sync(0xffffffffu, pv, o);
        if ((tid & 31) == 0) atomicAdd(&es[c], pv);
    }
    __syncthreads();

    if (tid < 32) {
        int c = tid;
        float m = es[c] * (1.0f / 448.0f);
        float avg = -BETA * logf(m);
        float rate = 0.83f * log2f(fmaf(0.73f, avg, 1.0f));

        float best = rate;
        int bi = c;
#pragma unroll
        for (int o = 16; o > 0; o >>= 1) {
            float orate = __shfl_down_sync(0xffffffffu, best, o);
            int   oidx  = __shfl_down_sync(0xffffffffu, bi, o);
            if (orate > best || (orate == best && oidx < bi)) { best = orate; bi = oidx; }
        }
        if (c == 0) {
            out[rb]       = (float)bi;
            out[256 + rb] = best;
            if (out_size >= 2560) {
                float* pd = out + 512 + rb * 8;
#pragma unroll
                for (int t = 0; t < 4; t++) {
                    float2 w = g_W[bi * 4 + t];
                    pd[2 * t]     = w.x;
                    pd[2 * t + 1] = w.y;
                }
            } else if (out_size >= 1536) {
                float* pd = out + 512 + rb * 4;
#pragma unroll
                for (int t = 0; t < 4; t++) pd[t] = g_W[bi * 4 + t].x;
            }
        }
    }
}

extern "C" void kernel_launch(void* const* d_in, const int* in_sizes, int n_in,
                              void* d_out, int out_size) {
    const float* hre = (const float*)d_in[0];
    const float* him = (const float*)d_in[1];
    float* out = (float*)d_out;

    k1_rb_average<<<32 * 14 * 8, dim3(32, 8)>>>(hre, him);
    k2_accum_R<<<NSITES / 256, 256>>>();
    k3_codebook_nv<<<1, 32>>>();
    k4_main<<<RB_DIM, 448>>>(out, out_size);
}

// round 4
// speedup vs baseline: 1.2623x; 1.2623x over previous
#include <cuda_runtime.h>

// Problem dims
#define A_DIM 32
#define R_DIM 2
#define T_DIM 4
#define S_DIM 14
#define F_DIM 3072
#define RB_DIM 256
#define NSITES (A_DIM * S_DIM * RB_DIM)   // 114688

#define BETA 2.71765f                      // 4.4492*ER^2 + 4.5655*ER + 1.2982, ER=0.25
#define SNR_LIN 10.0f
#define SQH 0.70710678118654752f

// Scratch (no allocation allowed)
__device__ float2 g_avg[NSITES * 8];       // [site][r*4+t], site = (a*14+s)*256+rb
__device__ float  g_R[32];                 // 4x4 complex R_{tu}, interleaved re/im
__device__ float  g_nv[32];                // noise variance per precoder
__device__ float2 g_W[32 * 4];             // codebook
__device__ float  g_rate[RB_DIM * 32];     // per (rb, c) rate

static __device__ __forceinline__ float2 cmul(float2 a, float2 b) {
    return make_float2(a.x * b.x - a.y * b.y, a.x * b.y + a.y * b.x);
}

// ---------------------------------------------------------------------------
// K1: average groups of 12 subcarriers -> site-major avg layout.
// grid: 32a * 14s * 8rbt = 3584 blocks, block (32 rbl, 8 rt)
// ---------------------------------------------------------------------------
__global__ void k1_rb_average(const float* __restrict__ hre,
                              const float* __restrict__ him) {
    int b = blockIdx.x;
    int rbt = b & 7;
    int s   = (b >> 3) % 14;
    int a   = b / 112;
    int rbl = threadIdx.x;      // 0..31
    int rt  = threadIdx.y;      // 0..7  (r*4+t)
    int r = rt >> 2, t = rt & 3;

    int base = ((((a * 2 + r) * 4 + t) * 14) + s) * F_DIM + (rbt * 32 + rbl) * 12;

    float4 r0 = *(const float4*)(hre + base);
    float4 r1 = *(const float4*)(hre + base + 4);
    float4 r2 = *(const float4*)(hre + base + 8);
    float4 i0 = *(const float4*)(him + base);
    float4 i1 = *(const float4*)(him + base + 4);
    float4 i2 = *(const float4*)(him + base + 8);

    float sr = (r0.x + r0.y) + (r0.z + r0.w) + (r1.x + r1.y) + (r1.z + r1.w)
             + (r2.x + r2.y) + (r2.z + r2.w);
    float si = (i0.x + i0.y) + (i0.z + i0.w) + (i1.x + i1.y) + (i1.z + i1.w)
             + (i2.x + i2.y) + (i2.z + i2.w);

    __shared__ float2 tile[32][9];
    tile[rbl][rt] = make_float2(sr * (1.0f / 12.0f), si * (1.0f / 12.0f));
    __syncthreads();

    int q   = rt * 32 + rbl;          // 0..255
    int lo  = q >> 3;                 // local site 0..31
    int rt2 = q & 7;
    int siteBase = (a * 14 + s) * 256 + rbt * 32;
    g_avg[(siteBase + lo) * 8 + rt2] = tile[lo][rt2];

    if (b == 0 && q < 32) g_R[q] = 0.0f;   // zero R before K2 (stream-ordered)
}

// ---------------------------------------------------------------------------
// K2: accumulate R_{tu} = sum over sites,r of h_t * conj(h_u)
// grid: 448 blocks of 256 (exactly NSITES threads)
// ---------------------------------------------------------------------------
__global__ void k2_accum_R() {
    int site = blockIdx.x * 256 + threadIdx.x;
    float2 h[8];
    const float4* p = (const float4*)(g_avg + site * 8);
    float4 v0 = p[0], v1 = p[1], v2 = p[2], v3 = p[3];
    h[0] = make_float2(v0.x, v0.y); h[1] = make_float2(v0.z, v0.w);
    h[2] = make_float2(v1.x, v1.y); h[3] = make_float2(v1.z, v1.w);
    h[4] = make_float2(v2.x, v2.y); h[5] = make_float2(v2.z, v2.w);
    h[6] = make_float2(v3.x, v3.y); h[7] = make_float2(v3.z, v3.w);

    float accRe[16], accIm[16];
#pragma unroll
    for (int t = 0; t < 4; t++) {
#pragma unroll
        for (int u = 0; u < 4; u++) {
            float re = 0.f, im = 0.f;
#pragma unroll
            for (int r = 0; r < 2; r++) {
                float2 x = h[r * 4 + t], y = h[r * 4 + u];
                re += x.x * y.x + x.y * y.y;   // x * conj(y)
                im += x.y * y.x - x.x * y.y;
            }
            accRe[t * 4 + u] = re;
            accIm[t * 4 + u] = im;
        }
    }

    __shared__ float red[8][32];
    int lane = threadIdx.x & 31, wid = threadIdx.x >> 5;
#pragma unroll
    for (int k = 0; k < 16; k++) {
        float vr = accRe[k], vi = accIm[k];
#pragma unroll
        for (int o = 16; o > 0; o >>= 1) {
            vr += __shfl_down_sync(0xffffffffu, vr, o);
            vi += __shfl_down_sync(0xffffffffu, vi, o);
        }
        if (lane == 0) { red[wid][2 * k] = vr; red[wid][2 * k + 1] = vi; }
    }
    __syncthreads();
    if (threadIdx.x < 32) {
        float v = 0.f;
#pragma unroll
        for (int w = 0; w < 8; w++) v += red[w][threadIdx.x];
        atomicAdd(&g_R[threadIdx.x], v);
    }
}

// ---------------------------------------------------------------------------
// K3: codebook + n_var per precoder.  1 block, 32 threads.
// ---------------------------------------------------------------------------
__global__ void k3_codebook_nv() {
    int c = threadIdx.x;
    int l = c >> 2, n = c & 3;
    float th = 0.78539816339744831f * (float)l;  // pi*l/4
    float cs, sn;
    __sincosf(th, &sn, &cs);
    float2 e   = make_float2(cs, sn);
    float2 phi = make_float2((n == 0) ? 1.f : (n == 2) ? -1.f : 0.f,
                             (n == 1) ? 1.f : (n == 3) ? -1.f : 0.f);
    float2 w[4];
    w[0] = make_float2(0.5f, 0.0f);
    w[1] = make_float2(0.5f * e.x, 0.5f * e.y);
    w[2] = make_float2(0.5f * phi.x, 0.5f * phi.y);
    float2 pe = cmul(phi, e);
    w[3] = make_float2(0.5f * pe.x, 0.5f * pe.y);
#pragma unroll
    for (int t = 0; t < 4; t++) g_W[c * 4 + t] = w[t];

    float acc = 0.f;
#pragma unroll
    for (int t = 0; t < 4; t++) {
#pragma unroll
        for (int u = 0; u < 4; u++) {
            float Rre = g_R[2 * (t * 4 + u)];
            float Rim = g_R[2 * (t * 4 + u) + 1];
            float zre = w[t].x * w[u].x + w[t].y * w[u].y;
            float zim = w[t].y * w[u].x - w[t].x * w[u].y;
            acc += zre * Rre - zim * Rim;
        }
    }
    g_nv[c] = acc / ((float)NSITES * SNR_LIN);
}

// ---------------------------------------------------------------------------
// K4: per-(rb, c-half) sinr/exp reduction over sites for 16 precoders.
// grid: 512 blocks (rb*2 + chalf), 448 threads (one site each).
// Codebook structure: w = 0.5*[1, e_l, phi_n, phi_n*e_l], phi_n = i^n.
// heff_r = A_r + e_l*B_r with A_r = 0.5*(h_r0 + phi*h_r2), B_r = 0.5*(h_r1 + phi*h_r3)
// Reduction: multi-value butterfly — 16 values reduced across 32 lanes in
// 8+4+2+1+1 = 16 shuffles; after the tree, lanes 2k,2k+1 hold the total for
// value ci = (lane>>1)&15.
// ---------------------------------------------------------------------------
__global__ void __launch_bounds__(448) k4_sinr() {
    const float EC[8]  = {1.f, SQH, 0.f, -SQH, -1.f, -SQH, 0.f, SQH};   // cos(pi*l/4)
    const float ESN[8] = {0.f, SQH, 1.f, SQH, 0.f, -SQH, -1.f, -SQH};   // sin(pi*l/4)
    const float PC[4]  = {1.f, 0.f, -1.f, 0.f};                         // Re(i^n)
    const float PS[4]  = {0.f, 1.f, 0.f, -1.f};                         // Im(i^n)

    int b  = blockIdx.x;
    int rb = b >> 1, ch = b & 1;
    int tid  = threadIdx.x;          // 448 sites: a = tid&31, s = tid>>5
    int lane = tid & 31, wid = tid >> 5;
    int site = ((tid & 31) * 14 + (tid >> 5)) * 256 + rb;

    float2 h[8];
    const float4* p = (const float4*)(g_avg + site * 8);
    float4 v0 = p[0], v1 = p[1], v2 = p[2], v3 = p[3];
    h[0] = make_float2(0.5f * v0.x, 0.5f * v0.y); h[1] = make_float2(0.5f * v0.z, 0.5f * v0.w);
    h[2] = make_float2(0.5f * v1.x, 0.5f * v1.y); h[3] = make_float2(0.5f * v1.z, 0.5f * v1.w);
    h[4] = make_float2(0.5f * v2.x, 0.5f * v2.y); h[5] = make_float2(0.5f * v2.z, 0.5f * v2.w);
    h[6] = make_float2(0.5f * v3.x, 0.5f * v3.y); h[7] = make_float2(0.5f * v3.z, 0.5f * v3.w);

    __shared__ float red[16][16];    // [ci][warp], 14 warps used
    __shared__ float nvs[16];
    if (tid < 16) nvs[tid] = g_nv[ch * 16 + tid];
    __syncthreads();

    float pvv[16];                   // pvv[ci], ci = j*4+n

#pragma unroll
    for (int n = 0; n < 4; n++) {
        const float pc = PC[n], ps = PS[n];
        float A0x = h[0].x + pc * h[2].x - ps * h[2].y;
        float A0y = h[0].y + pc * h[2].y + ps * h[2].x;
        float B0x = h[1].x + pc * h[3].x - ps * h[3].y;
        float B0y = h[1].y + pc * h[3].y + ps * h[3].x;
        float A1x = h[4].x + pc * h[6].x - ps * h[6].y;
        float A1y = h[4].y + pc * h[6].y + ps * h[6].x;
        float B1x = h[5].x + pc * h[7].x - ps * h[7].y;
        float B1y = h[5].y + pc * h[7].y + ps * h[7].x;

#pragma unroll
        for (int j = 0; j < 4; j++) {
            const int   l  = (ch << 2) + j;   // ch is uniform per block
            float ec, es;
            if (ch == 0) { ec = EC[j];     es = ESN[j];     }
            else         { ec = EC[j + 4]; es = ESN[j + 4]; }
            float e0x = A0x + ec * B0x - es * B0y;
            float e0y = A0y + ec * B0y + es * B0x;
            float e1x = A1x + ec * B1x - es * B1y;
            float e1y = A1y + ec * B1y + es * B1x;
            (void)l;

            float g  = e0x * e0x + e0y * e0y + e1x * e1x + e1y * e1y;
            float sx = e0x + e1x, sy = e0y + e1y;
            float u  = sx * sx + sy * sy;

            int   ci = j * 4 + n;
            float nv = nvs[ci];
            float t  = nv * u;
            float Q  = fmaf(g, g, t);
            float g2 = g * g;
            float rp = fmaf(2.0f * t, g + nv, g2 * g);
            float sinr = __fdividef(Q * Q, nv * rp);
            pvv[ci] = __expf(-sinr * (1.0f / BETA));
        }
    }

    // Multi-value butterfly: 16 values -> distributed sums.
    float w8[8];
    {
        bool hi = (lane & 16) != 0;
#pragma unroll
        for (int j = 0; j < 8; j++) {
            float keep = hi ? pvv[j + 8] : pvv[j];
            float send = hi ? pvv[j]     : pvv[j + 8];
            w8[j] = keep + __shfl_xor_sync(0xffffffffu, send, 16);
        }
    }
    float w4[4];
    {
        bool hi = (lane & 8) != 0;
#pragma unroll
        for (int j = 0; j < 4; j++) {
            float keep = hi ? w8[j + 4] : w8[j];
            float send = hi ? w8[j]     : w8[j + 4];
            w4[j] = keep + __shfl_xor_sync(0xffffffffu, send, 8);
        }
    }
    float w2[2];
    {
        bool hi = (lane & 4) != 0;
#pragma unroll
        for (int j = 0; j < 2; j++) {
            float keep = hi ? w2[0] : w2[0];   // placeholder; overwritten below
            (void)keep;
            float k2 = hi ? w4[j + 2] : w4[j];
            float s2 = hi ? w4[j]     : w4[j + 2];
            w2[j] = k2 + __shfl_xor_sync(0xffffffffu, s2, 4);
        }
    }
    float w1;
    {
        bool hi = (lane & 2) != 0;
        float k1v = hi ? w2[1] : w2[0];
        float s1v = hi ? w2[0] : w2[1];
        w1 = k1v + __shfl_xor_sync(0xffffffffu, s1v, 2);
    }
    w1 += __shfl_xor_sync(0xffffffffu, w1, 1);
    // lane holds total for ci = bit(lane,4)*8 + bit(lane,3)*4 + bit(lane,2)*2 + bit(lane,1)
    {
        int ci = ((lane >> 4) & 1) * 8 + ((lane >> 3) & 1) * 4
               + ((lane >> 2) & 1) * 2 + ((lane >> 1) & 1);
        if ((lane & 1) == 0) red[ci][wid] = w1;
    }
    __syncthreads();

    if (tid < 16) {
        float m = 0.f;
#pragma unroll
        for (int w = 0; w < 14; w++) m += red[tid][w];
        m *= (1.0f / 448.0f);
        float avg  = -BETA * logf(m);
        float rate = 0.83f * log2f(fmaf(0.73f, avg, 1.0f));
        g_rate[rb * 32 + ch * 16 + tid] = rate;
    }
}

// ---------------------------------------------------------------------------
// K5: argmax over 32 precoders per rb + output.  grid 32, block 256 (warp/rb).
// ---------------------------------------------------------------------------
__global__ void k5_finalize(float* __restrict__ out, int out_size) {
    int rb   = blockIdx.x * 8 + (threadIdx.x >> 5);
    int lane = threadIdx.x & 31;

    float best = g_rate[rb * 32 + lane];
    int   bi   = lane;
#pragma unroll
    for (int o = 16; o > 0; o >>= 1) {
        float ob = __shfl_down_sync(0xffffffffu, best, o);
        int   oi = __shfl_down_sync(0xffffffffu, bi, o);
        if (ob > best || (ob == best && oi < bi)) { best = ob; bi = oi; }
    }
    if (lane == 0) {
        out[rb]       = (float)bi;
        out[256 + rb] = best;
        if (out_size >= 2560) {
            float* pd = out + 512 + rb * 8;
#pragma unroll
            for (int t = 0; t < 4; t++) {
                float2 w = g_W[bi * 4 + t];
                pd[2 * t]     = w.x;
                pd[2 * t + 1] = w.y;
            }
        } else if (out_size >= 1536) {
            float* pd = out + 512 + rb * 4;
#pragma unroll
            for (int t = 0; t < 4; t++) pd[t] = g_W[bi * 4 + t].x;
        }
    }
}

extern "C" void kernel_launch(void* const* d_in, const int* in_sizes, int n_in,
                              void* d_out, int out_size) {
    const float* hre = (const float*)d_in[0];
    const float* him = (const float*)d_in[1];
    float* out = (float*)d_out;

    k1_rb_average<<<32 * 14 * 8, dim3(32, 8)>>>(hre, him);
    k2_accum_R<<<NSITES / 256, 256>>>();
    k3_codebook_nv<<<1, 32>>>();
    k4_sinr<<<RB_DIM * 2, 448>>>();
    k5_finalize<<<32, 256>>>(out, out_size);
}

// round 5
// speedup vs baseline: 1.3524x; 1.0714x over previous
#include <cuda_runtime.h>

// Problem dims
#define A_DIM 32
#define R_DIM 2
#define T_DIM 4
#define S_DIM 14
#define F_DIM 3072
#define RB_DIM 256
#define NSITES (A_DIM * S_DIM * RB_DIM)   // 114688

#define BETA 2.71765f                      // 4.4492*ER^2 + 4.5655*ER + 1.2982, ER=0.25
#define SNR_LIN 10.0f
#define SQH 0.70710678118654752f

// Scratch (no allocation allowed). g_R statically zero; K5 re-zeroes it at the
// end of every launch so graph replays stay correct.
__device__ float2 g_avg[NSITES * 8];       // [site][r*4+t], site = (a*14+s)*256+rb
__device__ float  g_R[32] = {};            // 4x4 complex R_{tu}, interleaved re/im
__device__ float  g_rate[RB_DIM * 32];     // per (rb, c) rate

// ---------------------------------------------------------------------------
// K1: average groups of 12 subcarriers -> site-major avg layout, and
// accumulate the global Gram matrix R (fused former K2).
// grid: 32a * 14s * 8rbt = 3584 blocks, block (32 rbl, 8 rt)
// ---------------------------------------------------------------------------
__global__ void k1_rb_average(const float* __restrict__ hre,
                              const float* __restrict__ him) {
    int b = blockIdx.x;
    int rbt = b & 7;
    int s   = (b >> 3) % 14;
    int a   = b / 112;
    int rbl = threadIdx.x;      // 0..31
    int rt  = threadIdx.y;      // 0..7  (r*4+t)
    int r = rt >> 2, t = rt & 3;

    int base = ((((a * 2 + r) * 4 + t) * 14) + s) * F_DIM + (rbt * 32 + rbl) * 12;

    float4 r0 = *(const float4*)(hre + base);
    float4 r1 = *(const float4*)(hre + base + 4);
    float4 r2 = *(const float4*)(hre + base + 8);
    float4 i0 = *(const float4*)(him + base);
    float4 i1 = *(const float4*)(him + base + 4);
    float4 i2 = *(const float4*)(him + base + 8);

    float sr = (r0.x + r0.y) + (r0.z + r0.w) + (r1.x + r1.y) + (r1.z + r1.w)
             + (r2.x + r2.y) + (r2.z + r2.w);
    float si = (i0.x + i0.y) + (i0.z + i0.w) + (i1.x + i1.y) + (i1.z + i1.w)
             + (i2.x + i2.y) + (i2.z + i2.w);

    __shared__ float2 tile[32][9];
    tile[rbl][rt] = make_float2(sr * (1.0f / 12.0f), si * (1.0f / 12.0f));
    __syncthreads();

    int q   = rt * 32 + rbl;          // 0..255
    int lo  = q >> 3;                 // local site 0..31
    int rt2 = q & 7;
    int siteBase = (a * 14 + s) * 256 + rbt * 32;
    g_avg[(siteBase + lo) * 8 + rt2] = tile[lo][rt2];

    // ---- fused R accumulation: warp 0, one site per lane ----
    if (rt == 0) {
        int lane = rbl;
        float2 h[8];
#pragma unroll
        for (int k = 0; k < 8; k++) h[k] = tile[lane][k];

        float v[32];
#pragma unroll
        for (int tt = 0; tt < 4; tt++) {
#pragma unroll
            for (int uu = 0; uu < 4; uu++) {
                float re = 0.f, im = 0.f;
#pragma unroll
                for (int rr = 0; rr < 2; rr++) {
                    float2 x = h[rr * 4 + tt], y = h[rr * 4 + uu];
                    re += x.x * y.x + x.y * y.y;   // x * conj(y)
                    im += x.y * y.x - x.x * y.y;
                }
                v[2 * (tt * 4 + uu)]     = re;
                v[2 * (tt * 4 + uu) + 1] = im;
            }
        }
        // 32-value butterfly: lane L ends with sum over warp of v[L]
        float s16[16];
        {
            bool hi = (lane & 16) != 0;
#pragma unroll
            for (int j = 0; j < 16; j++) {
                float keep = hi ? v[j + 16] : v[j];
                float send = hi ? v[j]      : v[j + 16];
                s16[j] = keep + __shfl_xor_sync(0xffffffffu, send, 16);
            }
        }
        float s8[8];
        {
            bool hi = (lane & 8) != 0;
#pragma unroll
            for (int j = 0; j < 8; j++) {
                float keep = hi ? s16[j + 8] : s16[j];
                float send = hi ? s16[j]     : s16[j + 8];
                s8[j] = keep + __shfl_xor_sync(0xffffffffu, send, 8);
            }
        }
        float s4[4];
        {
            bool hi = (lane & 4) != 0;
#pragma unroll
            for (int j = 0; j < 4; j++) {
                float keep = hi ? s8[j + 4] : s8[j];
                float send = hi ? s8[j]     : s8[j + 4];
                s4[j] = keep + __shfl_xor_sync(0xffffffffu, send, 4);
            }
        }
        float s2[2];
        {
            bool hi = (lane & 2) != 0;
#pragma unroll
            for (int j = 0; j < 2; j++) {
                float keep = hi ? s4[j + 2] : s4[j];
                float send = hi ? s4[j]     : s4[j + 2];
                s2[j] = keep + __shfl_xor_sync(0xffffffffu, send, 2);
            }
        }
        float tot;
        {
            bool hi = (lane & 1) != 0;
            float keep = hi ? s2[1] : s2[0];
            float send = hi ? s2[0] : s2[1];
            tot = keep + __shfl_xor_sync(0xffffffffu, send, 1);
        }
        atomicAdd(&g_R[lane], tot);
    }
}

// ---------------------------------------------------------------------------
// K4: per-(rb, parity-of-l) sinr/exp reduction over sites for 16 precoders.
// grid: 512 blocks (rb*2 + ch), 448 threads (one site each).
// ch selects l parity: l = 2j + ch, so e_l in {1,i,-1,-i} (ch0) or
// s*(1+i)*{1,i,-1,-i} (ch1).  heff = A + e_l*B = A (+/-) D or A (+/-) iD with
// D = B (ch0) or D = e_1*B (ch1).  nv' = 4*nv absorbs the 0.5 codebook scale.
// ---------------------------------------------------------------------------
__global__ void __launch_bounds__(448) k4_sinr() {
    int b  = blockIdx.x;
    int rb = b >> 1, ch = b & 1;
    int tid  = threadIdx.x;          // 448 sites: a = tid&31, s = tid>>5
    int lane = tid & 31, wid = tid >> 5;
    int site = ((tid & 31) * 14 + (tid >> 5)) * 256 + rb;

    __shared__ float red[16][16];    // [ci][warp], 14 warps used
    __shared__ float nvs[16];        // nv' = 4*nv for local precoder ci=j*4+n

    if (tid < 16) {
        int j = tid >> 2, n = tid & 3;
        int l = 2 * j + ch;
        float sn, cs;
        __sincosf(0.78539816339744831f * (float)l, &sn, &cs);
        float pnx = (n == 0) ? 1.f : (n == 2) ? -1.f : 0.f;
        float pny = (n == 1) ? 1.f : (n == 3) ? -1.f : 0.f;
        float wx[4] = {1.f, cs, pnx, pnx * cs - pny * sn};
        float wy[4] = {0.f, sn, pny, pnx * sn + pny * cs};
        float acc = 0.f;
#pragma unroll
        for (int t = 0; t < 4; t++) {
#pragma unroll
            for (int u = 0; u < 4; u++) {
                float Rre = g_R[2 * (t * 4 + u)];
                float Rim = g_R[2 * (t * 4 + u) + 1];
                float zre = wx[t] * wx[u] + wy[t] * wy[u];
                float zim = wy[t] * wx[u] - wx[t] * wy[u];
                acc += zre * Rre - zim * Rim;
            }
        }
        // true nv has the 1/4 from |w|^2 scaling; nv' = 4*nv  ->  no 1/4 here
        nvs[tid] = acc * (1.0f / ((float)NSITES * SNR_LIN));
    }

    float2 h[8];
    const float4* p = (const float4*)(g_avg + site * 8);
    float4 v0 = p[0], v1 = p[1], v2 = p[2], v3 = p[3];
    h[0] = make_float2(v0.x, v0.y); h[1] = make_float2(v0.z, v0.w);
    h[2] = make_float2(v1.x, v1.y); h[3] = make_float2(v1.z, v1.w);
    h[4] = make_float2(v2.x, v2.y); h[5] = make_float2(v2.z, v2.w);
    h[6] = make_float2(v3.x, v3.y); h[7] = make_float2(v3.z, v3.w);
    __syncthreads();

    float pvv[16];

#define PV(e0x, e0y, e1x, e1y, ci) do {                                   \
        float _g  = (e0x)*(e0x) + (e0y)*(e0y) + (e1x)*(e1x) + (e1y)*(e1y);\
        float _sx = (e0x) + (e1x), _sy = (e0y) + (e1y);                   \
        float _u  = _sx * _sx + _sy * _sy;                                \
        float _nv = nvs[ci];                                              \
        float _t  = _nv * _u;                                             \
        float _Q  = fmaf(_g, _g, _t);                                     \
        float _rp = fmaf(2.0f * _t, _g + _nv, _g * _g * _g);              \
        float _si = __fdividef(_Q * _Q, _nv * _rp);                       \
        pvv[ci] = __expf(-_si * (1.0f / BETA));                           \
    } while (0)

#pragma unroll
    for (int n = 0; n < 4; n++) {
        // A_r = h_r0 + phi_n h_r2 ; B_r = h_r1 + phi_n h_r3 ; phi_n = i^n
        float A0x, A0y, B0x, B0y, A1x, A1y, B1x, B1y;
        if (n == 0) {
            A0x = h[0].x + h[2].x; A0y = h[0].y + h[2].y;
            B0x = h[1].x + h[3].x; B0y = h[1].y + h[3].y;
            A1x = h[4].x + h[6].x; A1y = h[4].y + h[6].y;
            B1x = h[5].x + h[7].x; B1y = h[5].y + h[7].y;
        } else if (n == 1) {
            A0x = h[0].x - h[2].y; A0y = h[0].y + h[2].x;
            B0x = h[1].x - h[3].y; B0y = h[1].y + h[3].x;
            A1x = h[4].x - h[6].y; A1y = h[4].y + h[6].x;
            B1x = h[5].x - h[7].y; B1y = h[5].y + h[7].x;
        } else if (n == 2) {
            A0x = h[0].x - h[2].x; A0y = h[0].y - h[2].y;
            B0x = h[1].x - h[3].x; B0y = h[1].y - h[3].y;
            A1x = h[4].x - h[6].x; A1y = h[4].y - h[6].y;
            B1x = h[5].x - h[7].x; B1y = h[5].y - h[7].y;
        } else {
            A0x = h[0].x + h[2].y; A0y = h[0].y - h[2].x;
            B0x = h[1].x + h[3].y; B0y = h[1].y - h[3].x;
            A1x = h[4].x + h[6].y; A1y = h[4].y - h[6].x;
            B1x = h[5].x + h[7].y; B1y = h[5].y - h[7].x;
        }

        // D = B (ch0) or e_1*B = s*( Bx-By, By+Bx ) (ch1)
        float D0x, D0y, D1x, D1y;
        if (ch == 0) {
            D0x = B0x; D0y = B0y; D1x = B1x; D1y = B1y;
        } else {
            D0x = SQH * (B0x - B0y); D0y = SQH * (B0y + B0x);
            D1x = SQH * (B1x - B1y); D1y = SQH * (B1y + B1x);
        }

        // j=0: A+D ; j=1: A+iD ; j=2: A-D ; j=3: A-iD
        PV(A0x + D0x, A0y + D0y, A1x + D1x, A1y + D1y, 0 * 4 + n);
        PV(A0x - D0y, A0y + D0x, A1x - D1y, A1y + D1x, 1 * 4 + n);
        PV(A0x - D0x, A0y - D0y, A1x - D1x, A1y - D1y, 2 * 4 + n);
        PV(A0x + D0y, A0y - D0x, A1x + D1y, A1y - D1x, 3 * 4 + n);
    }
#undef PV

    // Multi-value butterfly: 16 values -> distributed sums.
    float w8[8];
    {
        bool hi = (lane & 16) != 0;
#pragma unroll
        for (int j = 0; j < 8; j++) {
            float keep = hi ? pvv[j + 8] : pvv[j];
            float send = hi ? pvv[j]     : pvv[j + 8];
            w8[j] = keep + __shfl_xor_sync(0xffffffffu, send, 16);
        }
    }
    float w4[4];
    {
        bool hi = (lane & 8) != 0;
#pragma unroll
        for (int j = 0; j < 4; j++) {
            float keep = hi ? w8[j + 4] : w8[j];
            float send = hi ? w8[j]     : w8[j + 4];
            w4[j] = keep + __shfl_xor_sync(0xffffffffu, send, 8);
        }
    }
    float w2[2];
    {
        bool hi = (lane & 4) != 0;
#pragma unroll
        for (int j = 0; j < 2; j++) {
            float k2 = hi ? w4[j + 2] : w4[j];
            float s2 = hi ? w4[j]     : w4[j + 2];
            w2[j] = k2 + __shfl_xor_sync(0xffffffffu, s2, 4);
        }
    }
    float w1;
    {
        bool hi = (lane & 2) != 0;
        float k1v = hi ? w2[1] : w2[0];
        float s1v = hi ? w2[0] : w2[1];
        w1 = k1v + __shfl_xor_sync(0xffffffffu, s1v, 2);
    }
    w1 += __shfl_xor_sync(0xffffffffu, w1, 1);
    {
        int ci = ((lane >> 4) & 1) * 8 + ((lane >> 3) & 1) * 4
               + ((lane >> 2) & 1) * 2 + ((lane >> 1) & 1);
        if ((lane & 1) == 0) red[ci][wid] = w1;
    }
    __syncthreads();

    if (tid < 16) {
        float m = 0.f;
#pragma unroll
        for (int w = 0; w < 14; w++) m += red[tid][w];
        m *= (1.0f / 448.0f);
        float avg  = -BETA * logf(m);
        float rate = 0.83f * log2f(fmaf(0.73f, avg, 1.0f));
        int j = tid >> 2, n = tid & 3;
        int c = (2 * j + ch) * 4 + n;      // global precoder index
        g_rate[rb * 32 + c] = rate;
    }
}

// ---------------------------------------------------------------------------
// K5: argmax over 32 precoders per rb + output; also re-zero g_R for the
// next graph replay.  grid 32, block 256 (warp per rb).
// ---------------------------------------------------------------------------
__global__ void k5_finalize(float* __restrict__ out, int out_size) {
    int rb   = blockIdx.x * 8 + (threadIdx.x >> 5);
    int lane = threadIdx.x & 31;

    if (blockIdx.x == 0 && threadIdx.x < 32) g_R[threadIdx.x] = 0.0f;

    float best = g_rate[rb * 32 + lane];
    int   bi   = lane;
#pragma unroll
    for (int o = 16; o > 0; o >>= 1) {
        float ob = __shfl_down_sync(0xffffffffu, best, o);
        int   oi = __shfl_down_sync(0xffffffffu, bi, o);
        if (ob > best || (ob == best && oi < bi)) { best = ob; bi = oi; }
    }
    if (lane == 0) {
        out[rb]       = (float)bi;
        out[256 + rb] = best;

        // selected precoder w = 0.5*[1, e_l, phi_n, phi_n*e_l]
        int l = bi >> 2, n = bi & 3;
        float sn, cs;
        __sincosf(0.78539816339744831f * (float)l, &sn, &cs);
        float pnx = (n == 0) ? 1.f : (n == 2) ? -1.f : 0.f;
        float pny = (n == 1) ? 1.f : (n == 3) ? -1.f : 0.f;
        float wx[4] = {0.5f, 0.5f * cs, 0.5f * pnx, 0.5f * (pnx * cs - pny * sn)};
        float wy[4] = {0.0f, 0.5f * sn, 0.5f * pny, 0.5f * (pnx * sn + pny * cs)};

        if (out_size >= 2560) {
            float* pd = out + 512 + rb * 8;
#pragma unroll
            for (int t = 0; t < 4; t++) {
                pd[2 * t]     = wx[t];
                pd[2 * t + 1] = wy[t];
            }
        } else if (out_size >= 1536) {
            float* pd = out + 512 + rb * 4;
#pragma unroll
            for (int t = 0; t < 4; t++) pd[t] = wx[t];
        }
    }
}

extern "C" void kernel_launch(void* const* d_in, const int* in_sizes, int n_in,
                              void* d_out, int out_size) {
    const float* hre = (const float*)d_in[0];
    const float* him = (const float*)d_in[1];
    float* out = (float*)d_out;

    k1_rb_average<<<32 * 14 * 8, dim3(32, 8)>>>(hre, him);
    k4_sinr<<<RB_DIM * 2, 448>>>();
    k5_finalize<<<32, 256>>>(out, out_size);
}

// round 6
// speedup vs baseline: 1.4528x; 1.0743x over previous
#include <cuda_runtime.h>

// Problem dims
#define A_DIM 32
#define R_DIM 2
#define T_DIM 4
#define S_DIM 14
#define F_DIM 3072
#define RB_DIM 256
#define NSITES (A_DIM * S_DIM * RB_DIM)   // 114688

#define BETA 2.71765f                      // 4.4492*ER^2 + 4.5655*ER + 1.2982, ER=0.25
#define SNR_LIN 10.0f
#define SQH 0.70710678118654752f

// Scratch (no allocation allowed). g_R statically zero; K5 re-zeroes it at the
// end of every launch so graph replays stay correct.
__device__ float2 g_avg[NSITES * 8];       // [site][r*4+t], site = (a*14+s)*256+rb
__device__ float  g_R[32] = {};            // 4x4 complex R_{tu}, interleaved re/im
__device__ float  g_rate[RB_DIM * 32];     // per (rb, c) rate

// ---------------------------------------------------------------------------
// K1: RB-average with fully coalesced loads + fused Gram accumulation.
// grid: 448 blocks = (a*14+s), block 256 threads.
// Each block processes 8 rows (r,t) x (re,im) of 3072 floats each, fully
// coalesced float4 loads; thread k ends up with h[8] for site (a,s,rb=k)
// and writes 64B contiguous. Then per-block Gram reduce + 32 atomics.
// ---------------------------------------------------------------------------
__global__ void __launch_bounds__(256) k1_rb_average(const float* __restrict__ hre,
                                                     const float* __restrict__ him) {
    int as  = blockIdx.x;            // a*14 + s
    int tid = threadIdx.x;           // 0..255 == rb
    int lane = tid & 31, wid = tid >> 5;

    __shared__ float psum_re[768];
    __shared__ float psum_im[768];

    float2 h[8];

#pragma unroll 1
    for (int rt = 0; rt < 8; rt++) {
        int r = rt >> 2, t = rt & 3;
        // row base: ((((a*2+r)*4+t)*14)+s) * 3072 ; as = a*14+s
        int a = as / 14, s = as - a * 14;
        long rowf = ((long)(((a * 2 + r) * 4 + t) * 14 + s)) * F_DIM;
        const float4* pre = (const float4*)(hre + rowf);
        const float4* pim = (const float4*)(him + rowf);

        float4 x0 = pre[tid], x1 = pre[tid + 256], x2 = pre[tid + 512];
        float4 y0 = pim[tid], y1 = pim[tid + 256], y2 = pim[tid + 512];

        psum_re[tid]       = (x0.x + x0.y) + (x0.z + x0.w);
        psum_re[tid + 256] = (x1.x + x1.y) + (x1.z + x1.w);
        psum_re[tid + 512] = (x2.x + x2.y) + (x2.z + x2.w);
        psum_im[tid]       = (y0.x + y0.y) + (y0.z + y0.w);
        psum_im[tid + 256] = (y1.x + y1.y) + (y1.z + y1.w);
        psum_im[tid + 512] = (y2.x + y2.y) + (y2.z + y2.w);
        __syncthreads();

        float re = psum_re[3 * tid] + psum_re[3 * tid + 1] + psum_re[3 * tid + 2];
        float im = psum_im[3 * tid] + psum_im[3 * tid + 1] + psum_im[3 * tid + 2];
        h[rt] = make_float2(re * (1.0f / 12.0f), im * (1.0f / 12.0f));
        __syncthreads();
    }

    // Write site data: 64B contiguous per thread, 2KB per warp.
    {
        int site = as * 256 + tid;
        float4* dst = (float4*)(g_avg + site * 8);
        dst[0] = make_float4(h[0].x, h[0].y, h[1].x, h[1].y);
        dst[1] = make_float4(h[2].x, h[2].y, h[3].x, h[3].y);
        dst[2] = make_float4(h[4].x, h[4].y, h[5].x, h[5].y);
        dst[3] = make_float4(h[6].x, h[6].y, h[7].x, h[7].y);
    }

    // ---- fused Gram: per-thread 4x4 complex R partial, warp butterfly,
    //      cross-warp smem reduce, 32 atomics per block ----
    float v[32];
#pragma unroll
    for (int tt = 0; tt < 4; tt++) {
#pragma unroll
        for (int uu = 0; uu < 4; uu++) {
            float re = 0.f, im = 0.f;
#pragma unroll
            for (int rr = 0; rr < 2; rr++) {
                float2 x = h[rr * 4 + tt], y = h[rr * 4 + uu];
                re += x.x * y.x + x.y * y.y;   // x * conj(y)
                im += x.y * y.x - x.x * y.y;
            }
            v[2 * (tt * 4 + uu)]     = re;
            v[2 * (tt * 4 + uu) + 1] = im;
        }
    }
    // 32-value butterfly: lane L ends with warp-sum of v[L]
    float s16[16];
    {
        bool hi = (lane & 16) != 0;
#pragma unroll
        for (int j = 0; j < 16; j++) {
            float keep = hi ? v[j + 16] : v[j];
            float send = hi ? v[j]      : v[j + 16];
            s16[j] = keep + __shfl_xor_sync(0xffffffffu, send, 16);
        }
    }
    float s8v[8];
    {
        bool hi = (lane & 8) != 0;
#pragma unroll
        for (int j = 0; j < 8; j++) {
            float keep = hi ? s16[j + 8] : s16[j];
            float send = hi ? s16[j]     : s16[j + 8];
            s8v[j] = keep + __shfl_xor_sync(0xffffffffu, send, 8);
        }
    }
    float s4v[4];
    {
        bool hi = (lane & 4) != 0;
#pragma unroll
        for (int j = 0; j < 4; j++) {
            float keep = hi ? s8v[j + 4] : s8v[j];
            float send = hi ? s8v[j]     : s8v[j + 4];
            s4v[j] = keep + __shfl_xor_sync(0xffffffffu, send, 4);
        }
    }
    float s2v[2];
    {
        bool hi = (lane & 2) != 0;
#pragma unroll
        for (int j = 0; j < 2; j++) {
            float keep = hi ? s4v[j + 2] : s4v[j];
            float send = hi ? s4v[j]     : s4v[j + 2];
            s2v[j] = keep + __shfl_xor_sync(0xffffffffu, send, 2);
        }
    }
    float tot;
    {
        bool hi = (lane & 1) != 0;
        float keep = hi ? s2v[1] : s2v[0];
        float send = hi ? s2v[0] : s2v[1];
        tot = keep + __shfl_xor_sync(0xffffffffu, send, 1);
    }
    // cross-warp reduce in smem (reuse psum_re)
    __syncthreads();
    psum_re[wid * 32 + lane] = tot;
    __syncthreads();
    if (tid < 32) {
        float acc = 0.f;
#pragma unroll
        for (int w = 0; w < 8; w++) acc += psum_re[w * 32 + tid];
        atomicAdd(&g_R[tid], acc);
    }
}

// ---------------------------------------------------------------------------
// K4: per-(rb, parity-of-l) sinr/exp reduction over sites for 16 precoders.
// grid: 512 blocks (rb*2 + ch), 448 threads (one site each).
// ---------------------------------------------------------------------------
__global__ void __launch_bounds__(448) k4_sinr() {
    int b  = blockIdx.x;
    int rb = b >> 1, ch = b & 1;
    int tid  = threadIdx.x;          // 448 sites: a = tid&31, s = tid>>5
    int lane = tid & 31, wid = tid >> 5;
    int site = ((tid & 31) * 14 + (tid >> 5)) * 256 + rb;

    __shared__ float red[16][16];    // [ci][warp], 14 warps used
    __shared__ float nvs[16];        // nv' = 4*nv for local precoder ci=j*4+n

    if (tid < 16) {
        int j = tid >> 2, n = tid & 3;
        int l = 2 * j + ch;
        float sn, cs;
        __sincosf(0.78539816339744831f * (float)l, &sn, &cs);
        float pnx = (n == 0) ? 1.f : (n == 2) ? -1.f : 0.f;
        float pny = (n == 1) ? 1.f : (n == 3) ? -1.f : 0.f;
        float wx[4] = {1.f, cs, pnx, pnx * cs - pny * sn};
        float wy[4] = {0.f, sn, pny, pnx * sn + pny * cs};
        float acc = 0.f;
#pragma unroll
        for (int t = 0; t < 4; t++) {
#pragma unroll
            for (int u = 0; u < 4; u++) {
                float Rre = g_R[2 * (t * 4 + u)];
                float Rim = g_R[2 * (t * 4 + u) + 1];
                float zre = wx[t] * wx[u] + wy[t] * wy[u];
                float zim = wy[t] * wx[u] - wx[t] * wy[u];
                acc += zre * Rre - zim * Rim;
            }
        }
        nvs[tid] = acc * (1.0f / ((float)NSITES * SNR_LIN));
    }

    float2 h[8];
    const float4* p = (const float4*)(g_avg + site * 8);
    float4 v0 = p[0], v1 = p[1], v2 = p[2], v3 = p[3];
    h[0] = make_float2(v0.x, v0.y); h[1] = make_float2(v0.z, v0.w);
    h[2] = make_float2(v1.x, v1.y); h[3] = make_float2(v1.z, v1.w);
    h[4] = make_float2(v2.x, v2.y); h[5] = make_float2(v2.z, v2.w);
    h[6] = make_float2(v3.x, v3.y); h[7] = make_float2(v3.z, v3.w);
    __syncthreads();

    float pvv[16];

#define PV(e0x, e0y, e1x, e1y, ci) do {                                   \
        float _g  = (e0x)*(e0x) + (e0y)*(e0y) + (e1x)*(e1x) + (e1y)*(e1y);\
        float _sx = (e0x) + (e1x), _sy = (e0y) + (e1y);                   \
        float _u  = _sx * _sx + _sy * _sy;                                \
        float _nv = nvs[ci];                                              \
        float _t  = _nv * _u;                                             \
        float _Q  = fmaf(_g, _g, _t);                                     \
        float _rp = fmaf(2.0f * _t, _g + _nv, _g * _g * _g);              \
        float _si = __fdividef(_Q * _Q, _nv * _rp);                       \
        pvv[ci] = __expf(-_si * (1.0f / BETA));                           \
    } while (0)

#pragma unroll
    for (int n = 0; n < 4; n++) {
        float A0x, A0y, B0x, B0y, A1x, A1y, B1x, B1y;
        if (n == 0) {
            A0x = h[0].x + h[2].x; A0y = h[0].y + h[2].y;
            B0x = h[1].x + h[3].x; B0y = h[1].y + h[3].y;
            A1x = h[4].x + h[6].x; A1y = h[4].y + h[6].y;
            B1x = h[5].x + h[7].x; B1y = h[5].y + h[7].y;
        } else if (n == 1) {
            A0x = h[0].x - h[2].y; A0y = h[0].y + h[2].x;
            B0x = h[1].x - h[3].y; B0y = h[1].y + h[3].x;
            A1x = h[4].x - h[6].y; A1y = h[4].y + h[6].x;
            B1x = h[5].x - h[7].y; B1y = h[5].y + h[7].x;
        } else if (n == 2) {
            A0x = h[0].x - h[2].x; A0y = h[0].y - h[2].y;
            B0x = h[1].x - h[3].x; B0y = h[1].y - h[3].y;
            A1x = h[4].x - h[6].x; A1y = h[4].y - h[6].y;
            B1x = h[5].x - h[7].x; B1y = h[5].y - h[7].y;
        } else {
            A0x = h[0].x + h[2].y; A0y = h[0].y - h[2].x;
            B0x = h[1].x + h[3].y; B0y = h[1].y - h[3].x;
            A1x = h[4].x + h[6].y; A1y = h[4].y - h[6].x;
            B1x = h[5].x + h[7].y; B1y = h[5].y - h[7].x;
        }

        float D0x, D0y, D1x, D1y;
        if (ch == 0) {
            D0x = B0x; D0y = B0y; D1x = B1x; D1y = B1y;
        } else {
            D0x = SQH * (B0x - B0y); D0y = SQH * (B0y + B0x);
            D1x = SQH * (B1x - B1y); D1y = SQH * (B1y + B1x);
        }

        PV(A0x + D0x, A0y + D0y, A1x + D1x, A1y + D1y, 0 * 4 + n);
        PV(A0x - D0y, A0y + D0x, A1x - D1y, A1y + D1x, 1 * 4 + n);
        PV(A0x - D0x, A0y - D0y, A1x - D1x, A1y - D1y, 2 * 4 + n);
        PV(A0x + D0y, A0y - D0x, A1x + D1y, A1y - D1x, 3 * 4 + n);
    }
#undef PV

    // Multi-value butterfly: 16 values -> distributed sums.
    float w8[8];
    {
        bool hi = (lane & 16) != 0;
#pragma unroll
        for (int j = 0; j < 8; j++) {
            float keep = hi ? pvv[j + 8] : pvv[j];
            float send = hi ? pvv[j]     : pvv[j + 8];
            w8[j] = keep + __shfl_xor_sync(0xffffffffu, send, 16);
        }
    }
    float w4[4];
    {
        bool hi = (lane & 8) != 0;
#pragma unroll
        for (int j = 0; j < 4; j++) {
            float keep = hi ? w8[j + 4] : w8[j];
            float send = hi ? w8[j]     : w8[j + 4];
            w4[j] = keep + __shfl_xor_sync(0xffffffffu, send, 8);
        }
    }
    float w2[2];
    {
        bool hi = (lane & 4) != 0;
#pragma unroll
        for (int j = 0; j < 2; j++) {
            float k2 = hi ? w4[j + 2] : w4[j];
            float s2 = hi ? w4[j]     : w4[j + 2];
            w2[j] = k2 + __shfl_xor_sync(0xffffffffu, s2, 4);
        }
    }
    float w1;
    {
        bool hi = (lane & 2) != 0;
        float k1v = hi ? w2[1] : w2[0];
        float s1v = hi ? w2[0] : w2[1];
        w1 = k1v + __shfl_xor_sync(0xffffffffu, s1v, 2);
    }
    w1 += __shfl_xor_sync(0xffffffffu, w1, 1);
    {
        int ci = ((lane >> 4) & 1) * 8 + ((lane >> 3) & 1) * 4
               + ((lane >> 2) & 1) * 2 + ((lane >> 1) & 1);
        if ((lane & 1) == 0) red[ci][wid] = w1;
    }
    __syncthreads();

    if (tid < 16) {
        float m = 0.f;
#pragma unroll
        for (int w = 0; w < 14; w++) m += red[tid][w];
        m *= (1.0f / 448.0f);
        float avg  = -BETA * logf(m);
        float rate = 0.83f * log2f(fmaf(0.73f, avg, 1.0f));
        int j = tid >> 2, n = tid & 3;
        int c = (2 * j + ch) * 4 + n;      // global precoder index
        g_rate[rb * 32 + c] = rate;
    }
}

// ---------------------------------------------------------------------------
// K5: argmax over 32 precoders per rb + output; re-zero g_R for next replay.
// grid 32, block 256 (warp per rb).
// ---------------------------------------------------------------------------
__global__ void k5_finalize(float* __restrict__ out, int out_size) {
    int rb   = blockIdx.x * 8 + (threadIdx.x >> 5);
    int lane = threadIdx.x & 31;

    if (blockIdx.x == 0 && threadIdx.x < 32) g_R[threadIdx.x] = 0.0f;

    float best = g_rate[rb * 32 + lane];
    int   bi   = lane;
#pragma unroll
    for (int o = 16; o > 0; o >>= 1) {
        float ob = __shfl_down_sync(0xffffffffu, best, o);
        int   oi = __shfl_down_sync(0xffffffffu, bi, o);
        if (ob > best || (ob == best && oi < bi)) { best = ob; bi = oi; }
    }
    if (lane == 0) {
        out[rb]       = (float)bi;
        out[256 + rb] = best;

        int l = bi >> 2, n = bi & 3;
        float sn, cs;
        __sincosf(0.78539816339744831f * (float)l, &sn, &cs);
        float pnx = (n == 0) ? 1.f : (n == 2) ? -1.f : 0.f;
        float pny = (n == 1) ? 1.f : (n == 3) ? -1.f : 0.f;
        float wx[4] = {0.5f, 0.5f * cs, 0.5f * pnx, 0.5f * (pnx * cs - pny * sn)};
        float wy[4] = {0.0f, 0.5f * sn, 0.5f * pny, 0.5f * (pnx * sn + pny * cs)};

        if (out_size >= 2560) {
            float* pd = out + 512 + rb * 8;
#pragma unroll
            for (int t = 0; t < 4; t++) {
                pd[2 * t]     = wx[t];
                pd[2 * t + 1] = wy[t];
            }
        } else if (out_size >= 1536) {
            float* pd = out + 512 + rb * 4;
#pragma unroll
            for (int t = 0; t < 4; t++) pd[t] = wx[t];
        }
    }
}

extern "C" void kernel_launch(void* const* d_in, const int* in_sizes, int n_in,
                              void* d_out, int out_size) {
    const float* hre = (const float*)d_in[0];
    const float* him = (const float*)d_in[1];
    float* out = (float*)d_out;

    k1_rb_average<<<448, 256>>>(hre, him);
    k4_sinr<<<RB_DIM * 2, 448>>>();
    k5_finalize<<<32, 256>>>(out, out_size);
}

// round 9
// speedup vs baseline: 1.5575x; 1.0721x over previous
#include <cuda_runtime.h>

// Problem dims
#define A_DIM 32
#define R_DIM 2
#define T_DIM 4
#define S_DIM 14
#define F_DIM 3072
#define RB_DIM 256
#define NSITES (A_DIM * S_DIM * RB_DIM)   // 114688

#define BETA 2.71765f                      // 4.4492*ER^2 + 4.5655*ER + 1.2982, ER=0.25
#define SNR_LIN 10.0f
#define SQH 0.70710678118654752f

// Scratch (no allocation allowed). g_R statically zero; K5 re-zeroes it at the
// end of every launch so graph replays stay correct.
// g_R layout (16): [0..3] diag real R_tt ; [4+2p,5+2p] complex R_tu for
// pairs p: (0,1),(0,2),(0,3),(1,2),(1,3),(2,3)
__device__ float2 g_avg[NSITES * 8];       // [site][r*4+t], site = (a*14+s)*256+rb
__device__ float  g_R[16] = {};
__device__ float  g_rate[RB_DIM * 32];     // per (rb, c) rate

// ---------------------------------------------------------------------------
// K1: RB-average, fully coalesced, split over (as, r): 896 blocks x 256 thr.
// Block handles 4 rows (t=0..3) of re+im for one (a,s,r); thread k ends with
// h[4] (complex) for rb=k and writes 32B contiguous. Fused Hermitian Gram
// partial (16 values) + butterfly + 16 atomics per block.
// ---------------------------------------------------------------------------
__global__ void __launch_bounds__(256) k1_rb_average(const float* __restrict__ hre,
                                                     const float* __restrict__ him) {
    int b   = blockIdx.x;
    int as  = b >> 1;                // a*14 + s
    int r   = b & 1;
    int tid = threadIdx.x;           // 0..255 == rb
    int lane = tid & 31, wid = tid >> 5;
    int a = as / 14, s = as - a * 14;

    __shared__ float psum_re[2][768];
    __shared__ float psum_im[2][768];
    __shared__ float red[16][8];

    float2 h[4];

#pragma unroll
    for (int t = 0; t < 4; t++) {
        long rowf = ((long)(((a * 2 + r) * 4 + t) * 14 + s)) * F_DIM;
        const float4* pre = (const float4*)(hre + rowf);
        const float4* pim = (const float4*)(him + rowf);

        float4 x0 = pre[tid], x1 = pre[tid + 256], x2 = pre[tid + 512];
        float4 y0 = pim[tid], y1 = pim[tid + 256], y2 = pim[tid + 512];

        int buf = t & 1;
        psum_re[buf][tid]       = (x0.x + x0.y) + (x0.z + x0.w);
        psum_re[buf][tid + 256] = (x1.x + x1.y) + (x1.z + x1.w);
        psum_re[buf][tid + 512] = (x2.x + x2.y) + (x2.z + x2.w);
        psum_im[buf][tid]       = (y0.x + y0.y) + (y0.z + y0.w);
        psum_im[buf][tid + 256] = (y1.x + y1.y) + (y1.z + y1.w);
        psum_im[buf][tid + 512] = (y2.x + y2.y) + (y2.z + y2.w);
        __syncthreads();

        float re = psum_re[buf][3 * tid] + psum_re[buf][3 * tid + 1] + psum_re[buf][3 * tid + 2];
        float im = psum_im[buf][3 * tid] + psum_im[buf][3 * tid + 1] + psum_im[buf][3 * tid + 2];
        h[t] = make_float2(re * (1.0f / 12.0f), im * (1.0f / 12.0f));
    }

    // Write site data: 32B contiguous per thread (site*8 + r*4 + t layout).
    {
        int site = as * 256 + tid;
        float4* dst = (float4*)(g_avg + site * 8 + r * 4);
        dst[0] = make_float4(h[0].x, h[0].y, h[1].x, h[1].y);
        dst[1] = make_float4(h[2].x, h[2].y, h[3].x, h[3].y);
    }

    // ---- fused Hermitian Gram: 4 diag (real) + 6 upper-tri (complex) ----
    float v[16];
#pragma unroll
    for (int t = 0; t < 4; t++)
        v[t] = h[t].x * h[t].x + h[t].y * h[t].y;
    {
        const int PT[6] = {0, 0, 0, 1, 1, 2};
        const int PU[6] = {1, 2, 3, 2, 3, 3};
#pragma unroll
        for (int p2 = 0; p2 < 6; p2++) {
            float2 x = h[PT[p2]], y = h[PU[p2]];
            v[4 + 2 * p2]     = x.x * y.x + x.y * y.y;   // Re(h_t conj(h_u))
            v[4 + 2 * p2 + 1] = x.y * y.x - x.x * y.y;   // Im
        }
    }

    // 16-value butterfly
    float w8[8];
    {
        bool hi = (lane & 16) != 0;
#pragma unroll
        for (int j = 0; j < 8; j++) {
            float keep = hi ? v[j + 8] : v[j];
            float send = hi ? v[j]     : v[j + 8];
            w8[j] = keep + __shfl_xor_sync(0xffffffffu, send, 16);
        }
    }
    float w4[4];
    {
        bool hi = (lane & 8) != 0;
#pragma unroll
        for (int j = 0; j < 4; j++) {
            float keep = hi ? w8[j + 4] : w8[j];
            float send = hi ? w8[j]     : w8[j + 4];
            w4[j] = keep + __shfl_xor_sync(0xffffffffu, send, 8);
        }
    }
    float w2[2];
    {
        bool hi = (lane & 4) != 0;
#pragma unroll
        for (int j = 0; j < 2; j++) {
            float k2 = hi ? w4[j + 2] : w4[j];
            float s2 = hi ? w4[j]     : w4[j + 2];
            w2[j] = k2 + __shfl_xor_sync(0xffffffffu, s2, 4);
        }
    }
    float w1;
    {
        bool hi = (lane & 2) != 0;
        float k1v = hi ? w2[1] : w2[0];
        float s1v = hi ? w2[0] : w2[1];
        w1 = k1v + __shfl_xor_sync(0xffffffffu, s1v, 2);
    }
    w1 += __shfl_xor_sync(0xffffffffu, w1, 1);
    {
        int ci = ((lane >> 4) & 1) * 8 + ((lane >> 3) & 1) * 4
               + ((lane >> 2) & 1) * 2 + ((lane >> 1) & 1);
        if ((lane & 1) == 0) red[ci][wid] = w1;
    }
    __syncthreads();

    if (tid < 16) {
        float acc = 0.f;
#pragma unroll
        for (int w = 0; w < 8; w++) acc += red[tid][w];
        atomicAdd(&g_R[tid], acc);
    }
}

// ---------------------------------------------------------------------------
// K4: per-(rb, parity-of-l) sinr/exp reduction over sites for 16 precoders.
// grid: 512 blocks (rb*2 + ch), 448 threads (one site each).
// ---------------------------------------------------------------------------
__global__ void __launch_bounds__(448) k4_sinr() {
    int b  = blockIdx.x;
    int rb = b >> 1, ch = b & 1;
    int tid  = threadIdx.x;          // 448 sites: a = tid&31, s = tid>>5
    int lane = tid & 31, wid = tid >> 5;
    int site = ((tid & 31) * 14 + (tid >> 5)) * 256 + rb;

    __shared__ float red[16][16];    // [ci][warp], 14 warps used
    __shared__ float nvs[16];        // nv' = 4*nv for local precoder ci=j*4+n

    if (tid < 16) {
        int j = tid >> 2, n = tid & 3;
        int l = 2 * j + ch;
        float sn, cs;
        __sincosf(0.78539816339744831f * (float)l, &sn, &cs);
        float pnx = (n == 0) ? 1.f : (n == 2) ? -1.f : 0.f;
        float pny = (n == 1) ? 1.f : (n == 3) ? -1.f : 0.f;
        float wx[4] = {1.f, cs, pnx, pnx * cs - pny * sn};
        float wy[4] = {0.f, sn, pny, pnx * sn + pny * cs};
        // diag: |w_t|^2 = 1 for all t
        float acc = g_R[0] + g_R[1] + g_R[2] + g_R[3];
        const int PT[6] = {0, 0, 0, 1, 1, 2};
        const int PU[6] = {1, 2, 3, 2, 3, 3};
#pragma unroll
        for (int p2 = 0; p2 < 6; p2++) {
            int t = PT[p2], u = PU[p2];
            float Rre = g_R[4 + 2 * p2];
            float Rim = g_R[4 + 2 * p2 + 1];
            float zre = wx[t] * wx[u] + wy[t] * wy[u];
            float zim = wy[t] * wx[u] - wx[t] * wy[u];
            acc += 2.0f * (zre * Rre - zim * Rim);
        }
        nvs[tid] = acc * (1.0f / ((float)NSITES * SNR_LIN));
    }

    float2 h[8];
    const float4* p = (const float4*)(g_avg + site * 8);
    float4 v0 = p[0], v1 = p[1], v2 = p[2], v3 = p[3];
    h[0] = make_float2(v0.x, v0.y); h[1] = make_float2(v0.z, v0.w);
    h[2] = make_float2(v1.x, v1.y); h[3] = make_float2(v1.z, v1.w);
    h[4] = make_float2(v2.x, v2.y); h[5] = make_float2(v2.z, v2.w);
    h[6] = make_float2(v3.x, v3.y); h[7] = make_float2(v3.z, v3.w);
    __syncthreads();

    float pvv[16];

#define PV(e0x, e0y, e1x, e1y, ci) do {                                   \
        float _g  = (e0x)*(e0x) + (e0y)*(e0y) + (e1x)*(e1x) + (e1y)*(e1y);\
        float _sx = (e0x) + (e1x), _sy = (e0y) + (e1y);                   \
        float _u  = _sx * _sx + _sy * _sy;                                \
        float _nv = nvs[ci];                                              \
        float _t  = _nv * _u;                                             \
        float _Q  = fmaf(_g, _g, _t);                                     \
        float _rp = fmaf(2.0f * _t, _g + _nv, _g * _g * _g);              \
        float _si = __fdividef(_Q * _Q, _nv * _rp);                       \
        pvv[ci] = __expf(-_si * (1.0f / BETA));                           \
    } while (0)

#pragma unroll
    for (int n = 0; n < 4; n++) {
        float A0x, A0y, B0x, B0y, A1x, A1y, B1x, B1y;
        if (n == 0) {
            A0x = h[0].x + h[2].x; A0y = h[0].y + h[2].y;
            B0x = h[1].x + h[3].x; B0y = h[1].y + h[3].y;
            A1x = h[4].x + h[6].x; A1y = h[4].y + h[6].y;
            B1x = h[5].x + h[7].x; B1y = h[5].y + h[7].y;
        } else if (n == 1) {
            A0x = h[0].x - h[2].y; A0y = h[0].y + h[2].x;
            B0x = h[1].x - h[3].y; B0y = h[1].y + h[3].x;
            A1x = h[4].x - h[6].y; A1y = h[4].y + h[6].x;
            B1x = h[5].x - h[7].y; B1y = h[5].y + h[7].x;
        } else if (n == 2) {
            A0x = h[0].x - h[2].x; A0y = h[0].y - h[2].y;
            B0x = h[1].x - h[3].x; B0y = h[1].y - h[3].y;
            A1x = h[4].x - h[6].x; A1y = h[4].y - h[6].y;
            B1x = h[5].x - h[7].x; B1y = h[5].y - h[7].y;
        } else {
            A0x = h[0].x + h[2].y; A0y = h[0].y - h[2].x;
            B0x = h[1].x + h[3].y; B0y = h[1].y - h[3].x;
            A1x = h[4].x + h[6].y; A1y = h[4].y - h[6].x;
            B1x = h[5].x + h[7].y; B1y = h[5].y - h[7].x;
        }

        float D0x, D0y, D1x, D1y;
        if (ch == 0) {
            D0x = B0x; D0y = B0y; D1x = B1x; D1y = B1y;
        } else {
            D0x = SQH * (B0x - B0y); D0y = SQH * (B0y + B0x);
            D1x = SQH * (B1x - B1y); D1y = SQH * (B1y + B1x);
        }

        PV(A0x + D0x, A0y + D0y, A1x + D1x, A1y + D1y, 0 * 4 + n);
        PV(A0x - D0y, A0y + D0x, A1x - D1y, A1y + D1x, 1 * 4 + n);
        PV(A0x - D0x, A0y - D0y, A1x - D1x, A1y - D1y, 2 * 4 + n);
        PV(A0x + D0y, A0y - D0x, A1x + D1y, A1y - D1x, 3 * 4 + n);
    }
#undef PV

    // Multi-value butterfly: 16 values -> distributed sums.
    float w8[8];
    {
        bool hi = (lane & 16) != 0;
#pragma unroll
        for (int j = 0; j < 8; j++) {
            float keep = hi ? pvv[j + 8] : pvv[j];
            float send = hi ? pvv[j]     : pvv[j + 8];
            w8[j] = keep + __shfl_xor_sync(0xffffffffu, send, 16);
        }
    }
    float w4[4];
    {
        bool hi = (lane & 8) != 0;
#pragma unroll
        for (int j = 0; j < 4; j++) {
            float keep = hi ? w8[j + 4] : w8[j];
            float send = hi ? w8[j]     : w8[j + 4];
            w4[j] = keep + __shfl_xor_sync(0xffffffffu, send, 8);
        }
    }
    float w2[2];
    {
        bool hi = (lane & 4) != 0;
#pragma unroll
        for (int j = 0; j < 2; j++) {
            float k2 = hi ? w4[j + 2] : w4[j];
            float s2 = hi ? w4[j]     : w4[j + 2];
            w2[j] = k2 + __shfl_xor_sync(0xffffffffu, s2, 4);
        }
    }
    float w1;
    {
        bool hi = (lane & 2) != 0;
        float k1v = hi ? w2[1] : w2[0];
        float s1v = hi ? w2[0] : w2[1];
        w1 = k1v + __shfl_xor_sync(0xffffffffu, s1v, 2);
    }
    w1 += __shfl_xor_sync(0xffffffffu, w1, 1);
    {
        int ci = ((lane >> 4) & 1) * 8 + ((lane >> 3) & 1) * 4
               + ((lane >> 2) & 1) * 2 + ((lane >> 1) & 1);
        if ((lane & 1) == 0) red[ci][wid] = w1;
    }
    __syncthreads();

    if (tid < 16) {
        float m = 0.f;
#pragma unroll
        for (int w = 0; w < 14; w++) m += red[tid][w];
        m *= (1.0f / 448.0f);
        float avg  = -BETA * logf(m);
        float rate = 0.83f * log2f(fmaf(0.73f, avg, 1.0f));
        int j = tid >> 2, n = tid & 3;
        int c = (2 * j + ch) * 4 + n;      // global precoder index
        g_rate[rb * 32 + c] = rate;
    }
}

// ---------------------------------------------------------------------------
// K5: argmax over 32 precoders per rb + output; re-zero g_R for next replay.
// grid 32, block 256 (warp per rb).
// ---------------------------------------------------------------------------
__global__ void k5_finalize(float* __restrict__ out, int out_size) {
    int rb   = blockIdx.x * 8 + (threadIdx.x >> 5);
    int lane = threadIdx.x & 31;

    if (blockIdx.x == 0 && threadIdx.x < 16) g_R[threadIdx.x] = 0.0f;

    float best = g_rate[rb * 32 + lane];
    int   bi   = lane;
#pragma unroll
    for (int o = 16; o > 0; o >>= 1) {
        float ob = __shfl_down_sync(0xffffffffu, best, o);
        int   oi = __shfl_down_sync(0xffffffffu, bi, o);
        if (ob > best || (ob == best && oi < bi)) { best = ob; bi = oi; }
    }
    if (lane == 0) {
        out[rb]       = (float)bi;
        out[256 + rb] = best;

        int l = bi >> 2, n = bi & 3;
        float sn, cs;
        __sincosf(0.78539816339744831f * (float)l, &sn, &cs);
        float pnx = (n == 0) ? 1.f : (n == 2) ? -1.f : 0.f;
        float pny = (n == 1) ? 1.f : (n == 3) ? -1.f : 0.f;
        float wx[4] = {0.5f, 0.5f * cs, 0.5f * pnx, 0.5f * (pnx * cs - pny * sn)};
        float wy[4] = {0.0f, 0.5f * sn, 0.5f * pny, 0.5f * (pnx * sn + pny * cs)};

        if (out_size >= 2560) {
            float* pd = out + 512 + rb * 8;
#pragma unroll
            for (int t = 0; t < 4; t++) {
                pd[2 * t]     = wx[t];
                pd[2 * t + 1] = wy[t];
            }
        } else if (out_size >= 1536) {
            float* pd = out + 512 + rb * 4;
#pragma unroll
            for (int t = 0; t < 4; t++) pd[t] = wx[t];
        }
    }
}

extern "C" void kernel_launch(void* const* d_in, const int* in_sizes, int n_in,
                              void* d_out, int out_size) {
    const float* hre = (const float*)d_in[0];
    const float* him = (const float*)d_in[1];
    float* out = (float*)d_out;

    k1_rb_average<<<896, 256>>>(hre, him);
    k4_sinr<<<RB_DIM * 2, 448>>>();
    k5_finalize<<<32, 256>>>(out, out_size);
}

// round 10
// speedup vs baseline: 1.5714x; 1.0089x over previous
#include <cuda_runtime.h>

// Problem dims
#define A_DIM 32
#define R_DIM 2
#define T_DIM 4
#define S_DIM 14
#define F_DIM 3072
#define RB_DIM 256
#define NSITES (A_DIM * S_DIM * RB_DIM)   // 114688

#define BETA 2.71765f                      // 4.4492*ER^2 + 4.5655*ER + 1.2982, ER=0.25
#define SNR_LIN 10.0f
#define SQH 0.70710678118654752f

// Scratch (no allocation allowed). g_R statically zero; K5 re-zeroes it at the
// end of every launch so graph replays stay correct.
// g_R layout (16): [0..3] diag real R_tt ; [4+2p,5+2p] complex R_tu for
// pairs p: (0,1),(0,2),(0,3),(1,2),(1,3),(2,3)
__device__ float2 g_avg[NSITES * 8];       // [site][r*4+t], site = (a*14+s)*256+rb
__device__ float  g_R[16] = {};
__device__ float  g_rate[RB_DIM * 32];     // per (rb, c) rate

// ---------------------------------------------------------------------------
// K1: RB-average, fully coalesced, split over (as, r): 896 blocks x 256 thr.
// ALL 24 LDG.128 issue before ONE block barrier (max MLP); per-t horizontal
// sums staged in psum[4][768]; after the barrier thread k gathers its RB's
// h[4] via stride-3 LDS (conflict-free). Fused Hermitian Gram (16 values)
// + butterfly + 16 atomics per block.
// ---------------------------------------------------------------------------
__global__ void __launch_bounds__(256, 2) k1_rb_average(const float* __restrict__ hre,
                                                        const float* __restrict__ him) {
    int b   = blockIdx.x;
    int as  = b >> 1;                // a*14 + s
    int r   = b & 1;
    int tid = threadIdx.x;           // 0..255 == rb
    int lane = tid & 31, wid = tid >> 5;
    int a = as / 14, s = as - a * 14;

    __shared__ float psum_re[4][768];
    __shared__ float psum_im[4][768];
    __shared__ float red[16][8];

#pragma unroll
    for (int t = 0; t < 4; t++) {
        long rowf = ((long)(((a * 2 + r) * 4 + t) * 14 + s)) * F_DIM;
        const float4* pre = (const float4*)(hre + rowf);
        const float4* pim = (const float4*)(him + rowf);

        float4 x0 = pre[tid], x1 = pre[tid + 256], x2 = pre[tid + 512];
        float4 y0 = pim[tid], y1 = pim[tid + 256], y2 = pim[tid + 512];

        psum_re[t][tid]       = (x0.x + x0.y) + (x0.z + x0.w);
        psum_re[t][tid + 256] = (x1.x + x1.y) + (x1.z + x1.w);
        psum_re[t][tid + 512] = (x2.x + x2.y) + (x2.z + x2.w);
        psum_im[t][tid]       = (y0.x + y0.y) + (y0.z + y0.w);
        psum_im[t][tid + 256] = (y1.x + y1.y) + (y1.z + y1.w);
        psum_im[t][tid + 512] = (y2.x + y2.y) + (y2.z + y2.w);
    }
    __syncthreads();

    float2 h[4];
#pragma unroll
    for (int t = 0; t < 4; t++) {
        float re = psum_re[t][3 * tid] + psum_re[t][3 * tid + 1] + psum_re[t][3 * tid + 2];
        float im = psum_im[t][3 * tid] + psum_im[t][3 * tid + 1] + psum_im[t][3 * tid + 2];
        h[t] = make_float2(re * (1.0f / 12.0f), im * (1.0f / 12.0f));
    }

    // Write site data: 32B contiguous per thread (site*8 + r*4 + t layout).
    {
        int site = as * 256 + tid;
        float4* dst = (float4*)(g_avg + site * 8 + r * 4);
        dst[0] = make_float4(h[0].x, h[0].y, h[1].x, h[1].y);
        dst[1] = make_float4(h[2].x, h[2].y, h[3].x, h[3].y);
    }

    // ---- fused Hermitian Gram: 4 diag (real) + 6 upper-tri (complex) ----
    float v[16];
#pragma unroll
    for (int t = 0; t < 4; t++)
        v[t] = h[t].x * h[t].x + h[t].y * h[t].y;
    {
        const int PT[6] = {0, 0, 0, 1, 1, 2};
        const int PU[6] = {1, 2, 3, 2, 3, 3};
#pragma unroll
        for (int p2 = 0; p2 < 6; p2++) {
            float2 x = h[PT[p2]], y = h[PU[p2]];
            v[4 + 2 * p2]     = x.x * y.x + x.y * y.y;   // Re(h_t conj(h_u))
            v[4 + 2 * p2 + 1] = x.y * y.x - x.x * y.y;   // Im
        }
    }

    // 16-value butterfly
    float w8[8];
    {
        bool hi = (lane & 16) != 0;
#pragma unroll
        for (int j = 0; j < 8; j++) {
            float keep = hi ? v[j + 8] : v[j];
            float send = hi ? v[j]     : v[j + 8];
            w8[j] = keep + __shfl_xor_sync(0xffffffffu, send, 16);
        }
    }
    float w4[4];
    {
        bool hi = (lane & 8) != 0;
#pragma unroll
        for (int j = 0; j < 4; j++) {
            float keep = hi ? w8[j + 4] : w8[j];
            float send = hi ? w8[j]     : w8[j + 4];
            w4[j] = keep + __shfl_xor_sync(0xffffffffu, send, 8);
        }
    }
    float w2[2];
    {
        bool hi = (lane & 4) != 0;
#pragma unroll
        for (int j = 0; j < 2; j++) {
            float k2 = hi ? w4[j + 2] : w4[j];
            float s2 = hi ? w4[j]     : w4[j + 2];
            w2[j] = k2 + __shfl_xor_sync(0xffffffffu, s2, 4);
        }
    }
    float w1;
    {
        bool hi = (lane & 2) != 0;
        float k1v = hi ? w2[1] : w2[0];
        float s1v = hi ? w2[0] : w2[1];
        w1 = k1v + __shfl_xor_sync(0xffffffffu, s1v, 2);
    }
    w1 += __shfl_xor_sync(0xffffffffu, w1, 1);
    {
        int ci = ((lane >> 4) & 1) * 8 + ((lane >> 3) & 1) * 4
               + ((lane >> 2) & 1) * 2 + ((lane >> 1) & 1);
        if ((lane & 1) == 0) red[ci][wid] = w1;
    }
    __syncthreads();

    if (tid < 16) {
        float acc = 0.f;
#pragma unroll
        for (int w = 0; w < 8; w++) acc += red[tid][w];
        atomicAdd(&g_R[tid], acc);
    }
}

// ---------------------------------------------------------------------------
// K4: per-(rb, parity-of-l) sinr/exp reduction over sites for 16 precoders.
// grid: 512 blocks (rb*2 + ch), 448 threads (one site each).
// ---------------------------------------------------------------------------
__global__ void __launch_bounds__(448) k4_sinr() {
    int b  = blockIdx.x;
    int rb = b >> 1, ch = b & 1;
    int tid  = threadIdx.x;          // 448 sites: a = tid&31, s = tid>>5
    int lane = tid & 31, wid = tid >> 5;
    int site = ((tid & 31) * 14 + (tid >> 5)) * 256 + rb;

    __shared__ float red[16][16];    // [ci][warp], 14 warps used
    __shared__ float nvs[16];        // nv' = 4*nv for local precoder ci=j*4+n

    if (tid < 16) {
        int j = tid >> 2, n = tid & 3;
        int l = 2 * j + ch;
        float sn, cs;
        __sincosf(0.78539816339744831f * (float)l, &sn, &cs);
        float pnx = (n == 0) ? 1.f : (n == 2) ? -1.f : 0.f;
        float pny = (n == 1) ? 1.f : (n == 3) ? -1.f : 0.f;
        float wx[4] = {1.f, cs, pnx, pnx * cs - pny * sn};
        float wy[4] = {0.f, sn, pny, pnx * sn + pny * cs};
        // diag: |w_t|^2 = 1 for all t
        float acc = g_R[0] + g_R[1] + g_R[2] + g_R[3];
        const int PT[6] = {0, 0, 0, 1, 1, 2};
        const int PU[6] = {1, 2, 3, 2, 3, 3};
#pragma unroll
        for (int p2 = 0; p2 < 6; p2++) {
            int t = PT[p2], u = PU[p2];
            float Rre = g_R[4 + 2 * p2];
            float Rim = g_R[4 + 2 * p2 + 1];
            float zre = wx[t] * wx[u] + wy[t] * wy[u];
            float zim = wy[t] * wx[u] - wx[t] * wy[u];
            acc += 2.0f * (zre * Rre - zim * Rim);
        }
        nvs[tid] = acc * (1.0f / ((float)NSITES * SNR_LIN));
    }

    float2 h[8];
    const float4* p = (const float4*)(g_avg + site * 8);
    float4 v0 = p[0], v1 = p[1], v2 = p[2], v3 = p[3];
    h[0] = make_float2(v0.x, v0.y); h[1] = make_float2(v0.z, v0.w);
    h[2] = make_float2(v1.x, v1.y); h[3] = make_float2(v1.z, v1.w);
    h[4] = make_float2(v2.x, v2.y); h[5] = make_float2(v2.z, v2.w);
    h[6] = make_float2(v3.x, v3.y); h[7] = make_float2(v3.z, v3.w);
    __syncthreads();

    float pvv[16];

#define PV(e0x, e0y, e1x, e1y, ci) do {                                   \
        float _g  = (e0x)*(e0x) + (e0y)*(e0y) + (e1x)*(e1x) + (e1y)*(e1y);\
        float _sx = (e0x) + (e1x), _sy = (e0y) + (e1y);                   \
        float _u  = _sx * _sx + _sy * _sy;                                \
        float _nv = nvs[ci];                                              \
        float _t  = _nv * _u;                                             \
        float _Q  = fmaf(_g, _g, _t);                                     \
        float _rp = fmaf(2.0f * _t, _g + _nv, _g * _g * _g);              \
        float _si = __fdividef(_Q * _Q, _nv * _rp);                       \
        pvv[ci] = __expf(-_si * (1.0f / BETA));                           \
    } while (0)

#pragma unroll
    for (int n = 0; n < 4; n++) {
        float A0x, A0y, B0x, B0y, A1x, A1y, B1x, B1y;
        if (n == 0) {
            A0x = h[0].x + h[2].x; A0y = h[0].y + h[2].y;
            B0x = h[1].x + h[3].x; B0y = h[1].y + h[3].y;
            A1x = h[4].x + h[6].x; A1y = h[4].y + h[6].y;
            B1x = h[5].x + h[7].x; B1y = h[5].y + h[7].y;
        } else if (n == 1) {
            A0x = h[0].x - h[2].y; A0y = h[0].y + h[2].x;
            B0x = h[1].x - h[3].y; B0y = h[1].y + h[3].x;
            A1x = h[4].x - h[6].y; A1y = h[4].y + h[6].x;
            B1x = h[5].x - h[7].y; B1y = h[5].y + h[7].x;
        } else if (n == 2) {
            A0x = h[0].x - h[2].x; A0y = h[0].y - h[2].y;
            B0x = h[1].x - h[3].x; B0y = h[1].y - h[3].y;
            A1x = h[4].x - h[6].x; A1y = h[4].y - h[6].y;
            B1x = h[5].x - h[7].x; B1y = h[5].y - h[7].y;
        } else {
            A0x = h[0].x + h[2].y; A0y = h[0].y - h[2].x;
            B0x = h[1].x + h[3].y; B0y = h[1].y - h[3].x;
            A1x = h[4].x + h[6].y; A1y = h[4].y - h[6].x;
            B1x = h[5].x + h[7].y; B1y = h[5].y - h[7].x;
        }

        float D0x, D0y, D1x, D1y;
        if (ch == 0) {
            D0x = B0x; D0y = B0y; D1x = B1x; D1y = B1y;
        } else {
            D0x = SQH * (B0x - B0y); D0y = SQH * (B0y + B0x);
            D1x = SQH * (B1x - B1y); D1y = SQH * (B1y + B1x);
        }

        PV(A0x + D0x, A0y + D0y, A1x + D1x, A1y + D1y, 0 * 4 + n);
        PV(A0x - D0y, A0y + D0x, A1x - D1y, A1y + D1x, 1 * 4 + n);
        PV(A0x - D0x, A0y - D0y, A1x - D1x, A1y - D1y, 2 * 4 + n);
        PV(A0x + D0y, A0y - D0x, A1x + D1y, A1y - D1x, 3 * 4 + n);
    }
#undef PV

    // Multi-value butterfly: 16 values -> distributed sums.
    float w8[8];
    {
        bool hi = (lane & 16) != 0;
#pragma unroll
        for (int j = 0; j < 8; j++) {
            float keep = hi ? pvv[j + 8] : pvv[j];
            float send = hi ? pvv[j]     : pvv[j + 8];
            w8[j] = keep + __shfl_xor_sync(0xffffffffu, send, 16);
        }
    }
    float w4[4];
    {
        bool hi = (lane & 8) != 0;
#pragma unroll
        for (int j = 0; j < 4; j++) {
            float keep = hi ? w8[j + 4] : w8[j];
            float send = hi ? w8[j]     : w8[j + 4];
            w4[j] = keep + __shfl_xor_sync(0xffffffffu, send, 8);
        }
    }
    float w2[2];
    {
        bool hi = (lane & 4) != 0;
#pragma unroll
        for (int j = 0; j < 2; j++) {
            float k2 = hi ? w4[j + 2] : w4[j];
            float s2 = hi ? w4[j]     : w4[j + 2];
            w2[j] = k2 + __shfl_xor_sync(0xffffffffu, s2, 4);
        }
    }
    float w1;
    {
        bool hi = (lane & 2) != 0;
        float k1v = hi ? w2[1] : w2[0];
        float s1v = hi ? w2[0] : w2[1];
        w1 = k1v + __shfl_xor_sync(0xffffffffu, s1v, 2);
    }
    w1 += __shfl_xor_sync(0xffffffffu, w1, 1);
    {
        int ci = ((lane >> 4) & 1) * 8 + ((lane >> 3) & 1) * 4
               + ((lane >> 2) & 1) * 2 + ((lane >> 1) & 1);
        if ((lane & 1) == 0) red[ci][wid] = w1;
    }
    __syncthreads();

    if (tid < 16) {
        float m = 0.f;
#pragma unroll
        for (int w = 0; w < 14; w++) m += red[tid][w];
        m *= (1.0f / 448.0f);
        float avg  = -BETA * logf(m);
        float rate = 0.83f * log2f(fmaf(0.73f, avg, 1.0f));
        int j = tid >> 2, n = tid & 3;
        int c = (2 * j + ch) * 4 + n;      // global precoder index
        g_rate[rb * 32 + c] = rate;
    }
}

// ---------------------------------------------------------------------------
// K5: argmax over 32 precoders per rb + output; re-zero g_R for next replay.
// grid 32, block 256 (warp per rb).
// ---------------------------------------------------------------------------
__global__ void k5_finalize(float* __restrict__ out, int out_size) {
    int rb   = blockIdx.x * 8 + (threadIdx.x >> 5);
    int lane = threadIdx.x & 31;

    if (blockIdx.x == 0 && threadIdx.x < 16) g_R[threadIdx.x] = 0.0f;

    float best = g_rate[rb * 32 + lane];
    int   bi   = lane;
#pragma unroll
    for (int o = 16; o > 0; o >>= 1) {
        float ob = __shfl_down_sync(0xffffffffu, best, o);
        int   oi = __shfl_down_sync(0xffffffffu, bi, o);
        if (ob > best || (ob == best && oi < bi)) { best = ob; bi = oi; }
    }
    if (lane == 0) {
        out[rb]       = (float)bi;
        out[256 + rb] = best;

        int l = bi >> 2, n = bi & 3;
        float sn, cs;
        __sincosf(0.78539816339744831f * (float)l, &sn, &cs);
        float pnx = (n == 0) ? 1.f : (n == 2) ? -1.f : 0.f;
        float pny = (n == 1) ? 1.f : (n == 3) ? -1.f : 0.f;
        float wx[4] = {0.5f, 0.5f * cs, 0.5f * pnx, 0.5f * (pnx * cs - pny * sn)};
        float wy[4] = {0.0f, 0.5f * sn, 0.5f * pny, 0.5f * (pnx * sn + pny * cs)};

        if (out_size >= 2560) {
            float* pd = out + 512 + rb * 8;
#pragma unroll
            for (int t = 0; t < 4; t++) {
                pd[2 * t]     = wx[t];
                pd[2 * t + 1] = wy[t];
            }
        } else if (out_size >= 1536) {
            float* pd = out + 512 + rb * 4;
#pragma unroll
            for (int t = 0; t < 4; t++) pd[t] = wx[t];
        }
    }
}

extern "C" void kernel_launch(void* const* d_in, const int* in_sizes, int n_in,
                              void* d_out, int out_size) {
    const float* hre = (const float*)d_in[0];
    const float* him = (const float*)d_in[1];
    float* out = (float*)d_out;

    k1_rb_average<<<896, 256>>>(hre, him);
    k4_sinr<<<RB_DIM * 2, 448>>>();
    k5_finalize<<<32, 256>>>(out, out_size);
}